// round 16
// baseline (speedup 1.0000x reference)
#include <cuda_runtime.h>
#include <cuda_fp16.h>
#include <cstdint>
#include <cstddef>

#define LTOK 4096   // H*W tokens
#define CCH  512    // in channels
#define CIN  256    // inter channels
#define NBAT 4      // batch
#define EPSV 1e-5f
#define FSHIFT 12.0f

// ---------------- scratch (device globals: no runtime allocation) ----------
__device__ __half d_xth[(size_t)NBAT * LTOK * CCH];  // x^T hi (L,C)
__device__ __half d_xtl[(size_t)NBAT * LTOK * CCH];  // x^T lo
__device__ __half d_thwh[CIN * CCH], d_thwl[CIN * CCH];
__device__ __half d_phwh[CIN * CCH], d_phwl[CIN * CCH];
__device__ __half d_gwh [CIN * CCH];
__device__ __half d_wzh [CCH * CIN];
__device__ __half d_thh[(size_t)NBAT * LTOK * CIN];  // theta^T hi only (L,CI)
__device__ __half d_phh[(size_t)NBAT * LTOK * CIN];  // phi^T hi
__device__ __half d_phl[(size_t)NBAT * LTOK * CIN];  // phi^T lo
__device__ __half d_gh [(size_t)NBAT * CIN * LTOK];  // g hi only (CI,L)
__device__ __half d_ph_[(size_t)NBAT * LTOK * LTOK]; // unnormalized exp(f-12) fp16
__device__ float  d_rsum[(size_t)NBAT * LTOK];       // softmax row sums
__device__ __half d_y2h[(size_t)NBAT * LTOK * CIN];  // y2 hi only (L,CI)
__device__ float d_wy[(size_t)NBAT * CCH * LTOK];
__device__ float d_cstat[2 * CCH];                   // channel sum / sumsq
__device__ float d_mean[CCH];
__device__ float d_rstd[CCH];

// =========================== helpers ========================================
__device__ __forceinline__ uint32_t smem_u32(const void* p) {
    uint32_t a;
    asm("{ .reg .u64 t; cvta.to.shared.u64 t, %1; cvt.u32.u64 %0, t; }" : "=r"(a) : "l"(p));
    return a;
}
// pack two fp32 into f16x2 (x -> low 16 bits, y -> high 16 bits)
__device__ __forceinline__ uint32_t cvt2h(float x, float y) {
    uint32_t r;
    asm("cvt.rn.f16x2.f32 %0, %1, %2;" : "=r"(r) : "f"(y), "f"(x));
    return r;
}
__device__ __forceinline__ void split2(float x, float y, uint32_t& h, uint32_t& l) {
    h = cvt2h(x, y);
    const float hx = __half2float(__ushort_as_half((unsigned short)(h & 0xffffu)));
    const float hy = __half2float(__ushort_as_half((unsigned short)(h >> 16)));
    l = cvt2h(x - hx, y - hy);
}
__device__ __forceinline__ void mma16816(float c[4], const uint32_t a[4],
                                         uint32_t b0, uint32_t b1) {
    asm volatile(
        "mma.sync.aligned.m16n8k16.row.col.f32.f16.f16.f32 "
        "{%0,%1,%2,%3}, {%4,%5,%6,%7}, {%8,%9}, {%0,%1,%2,%3};"
        : "+f"(c[0]), "+f"(c[1]), "+f"(c[2]), "+f"(c[3])
        : "r"(a[0]), "r"(a[1]), "r"(a[2]), "r"(a[3]), "r"(b0), "r"(b1));
}
__device__ __forceinline__ void ldm4(uint32_t r[4], uint32_t addr) {
    asm volatile("ldmatrix.sync.aligned.m8n8.x4.shared.b16 {%0,%1,%2,%3}, [%4];"
        : "=r"(r[0]), "=r"(r[1]), "=r"(r[2]), "=r"(r[3]) : "r"(addr));
}
__device__ __forceinline__ void cp16(uint32_t dst, const void* src) {
    asm volatile("cp.async.cg.shared.global [%0], [%1], 16;" :: "r"(dst), "l"(src) : "memory");
}
#define CP_COMMIT() asm volatile("cp.async.commit_group;" ::: "memory")
template<int N>
__device__ __forceinline__ void cp_wait() {
    asm volatile("cp.async.wait_group %0;" :: "n"(N) : "memory");
}

// ============ unified GEMM: fp16 split inputs, cp.async pipeline ============
// TERMS==2: D = Ah·(Bh+Bl)^T (A quantized fp16),  K-step 64, 2 stages
// TERMS==1: D = Ah·Bh^T (both quantized fp16),    K-step 64, 3 stages
// Row-major K-contig. CTA tile TMQ x TNQ (128/256), 64x64 warp tiles,
// 128 threads & 2 CTAs/SM for 128x128, 256 threads & 1 CTA/SM otherwise.
// Fragments via ldmatrix.x4 (non-trans).
// OUTM 0: fp32 D; 1: half Dh+Dl; 2: half Dh only;
// OUTM 3: exp epilogue — Dh = fp16 exp(acc-FSHIFT), D = fp32 rowsum atomics.
// OUTM 4: fp32 D + per-row (channel) sum/sumsq atomics into
//         csum=(float*)Dh, csq=(float*)Dl (shared across batch).
// BMODE 0: none, 1: bias per-M-row, 2: bias per-N-col,
// BMODE 3: row-scale by 1/bias[row] (bias = rowsum, batch stride LTOK).

template<int TERMS, int OUTM, int BMODE, int TMQ, int TNQ>
__global__ void __launch_bounds__(TMQ * TNQ / 128, (TMQ == 128 && TNQ == 128) ? 2 : 1)
gemm_pre(const __half* __restrict__ Ah,
         int lda, long long sA,
         const __half* __restrict__ Bh, const __half* __restrict__ Bl,
         int ldb, long long sB,
         float* __restrict__ D, __half* __restrict__ Dh,
         __half* __restrict__ Dl, int ldc, long long sD,
         const float* __restrict__ bias, int K)
{
    constexpr int THREADS = TMQ * TNQ / 128;
    constexpr int KS   = 64;                      // K per stage
    constexpr int CW   = KS / 2;                  // u32 per row (data)
    constexpr int STR  = CW + 4;                  // padded row stride (u32)
    constexpr int CPR  = CW / 4;                  // 16B chunks per row
    constexpr int SMA  = TMQ * STR;
    constexpr int SMB  = TNQ * STR;
    constexpr int gAH  = 0;
    constexpr int gBH  = SMA;
    constexpr int gBL  = SMA + SMB;               // TERMS==2 only
    constexpr int STG  = SMA + (TERMS == 2 ? 2 : 1) * SMB;
    constexpr int NSTG = (TERMS == 1) ? 3 : 2;
    constexpr int SSN  = KS / 16;
    constexpr int NW_M = TMQ / 64;

    extern __shared__ uint32_t sm[];
    const uint32_t sbase = smem_u32(sm);
    Ah += (size_t)blockIdx.z * sA;
    Bh += (size_t)blockIdx.z * sB;
    if (TERMS == 2) Bl += (size_t)blockIdx.z * sB;
    if (OUTM == 0 || OUTM == 4) D += (size_t)blockIdx.z * sD;
    else if (OUTM == 3) { Dh += (size_t)blockIdx.z * sD; D += (size_t)blockIdx.z * LTOK; }
    else { Dh += (size_t)blockIdx.z * sD; if (OUTM == 1) Dl += (size_t)blockIdx.z * sD; }
    if (BMODE == 3) bias += (size_t)blockIdx.z * LTOK;

    const int bm = blockIdx.y * TMQ;
    const int bn = blockIdx.x * TNQ;
    const int tid  = threadIdx.x;
    const int lane = tid & 31;
    const int wid  = tid >> 5;
    const int wm = (wid % NW_M) * 64;
    const int wn = (wid / NW_M) * 64;

    float acc[4][8][4];
#pragma unroll
    for (int a = 0; a < 4; a++)
#pragma unroll
        for (int b = 0; b < 8; b++)
#pragma unroll
            for (int c = 0; c < 4; c++) acc[a][b][c] = 0.f;

    const int KT = K / KS;

    auto issue = [&](int kt) {
        if (kt >= KT) return;
        const uint32_t sb = sbase + (uint32_t)(kt % NSTG) * (STG * 4);
        const int k0 = kt * KS;
#pragma unroll
        for (int p = 0; p < TMQ * CPR / THREADS; p++) {
            const int c = tid + p * THREADS;
            const int r = c / CPR, cc = c % CPR;
            const uint32_t d = sb + (uint32_t)((r * STR + cc * 4) << 2);
            cp16(d + gAH * 4, Ah + (size_t)(bm + r) * lda + k0 + cc * 8);
        }
#pragma unroll
        for (int p = 0; p < TNQ * CPR / THREADS; p++) {
            const int c = tid + p * THREADS;
            const int r = c / CPR, cc = c % CPR;
            const uint32_t d = sb + (uint32_t)((r * STR + cc * 4) << 2);
            const size_t goB = (size_t)(bn + r) * ldb + k0 + cc * 8;
            cp16(d + gBH * 4, Bh + goB);
            if (TERMS == 2) cp16(d + gBL * 4, Bl + goB);
        }
    };

#pragma unroll
    for (int s = 0; s < NSTG; s++) { issue(s); CP_COMMIT(); }

    // ldmatrix lane geometry (non-trans x4)
    const int aRow = (lane & 7) + (lane & 8);          // A: tiles (row-half, k-half)
    const int aCol = (lane >> 4) * 4;
    const int bRow = (lane & 7) + ((lane & 16) >> 1);  // B: tiles (k-half, n-half)
    const int bCol = ((lane >> 3) & 1) * 4;

    for (int kt = 0; kt < KT; kt++) {
        cp_wait<NSTG - 1>();
        __syncthreads();
        const uint32_t sb = sbase + (uint32_t)(kt % NSTG) * (STG * 4);
        uint32_t aBh[4], bB_h[4], bB_l[4];
#pragma unroll
        for (int mt = 0; mt < 4; mt++) {
            const uint32_t ro = (uint32_t)((wm + mt * 16 + aRow) * STR + aCol) * 4;
            aBh[mt] = sb + gAH * 4 + ro;
        }
#pragma unroll
        for (int np = 0; np < 4; np++) {
            const uint32_t ro = (uint32_t)((wn + np * 16 + bRow) * STR + bCol) * 4;
            bB_h[np] = sb + gBH * 4 + ro;
            if (TERMS == 2) bB_l[np] = sb + gBL * 4 + ro;
        }
#pragma unroll
        for (int ss = 0; ss < SSN; ss++) {
            const uint32_t o = ss * 32;   // 8 u32 per k16 step
            uint32_t Ahf[4][4], Bhf[4][4], Blf[4][4];
#pragma unroll
            for (int mt = 0; mt < 4; mt++) ldm4(Ahf[mt], aBh[mt] + o);
#pragma unroll
            for (int np = 0; np < 4; np++) {
                ldm4(Bhf[np], bB_h[np] + o);
                if (TERMS == 2) ldm4(Blf[np], bB_l[np] + o);
            }
#pragma unroll
            for (int nt = 0; nt < 8; nt++) {
                const int q = nt >> 1, h = (nt & 1) * 2;
                const uint32_t b0h = Bhf[q][h], b1h = Bhf[q][h + 1];
#pragma unroll
                for (int mt = 0; mt < 4; mt++) {
                    mma16816(acc[mt][nt], Ahf[mt], b0h, b1h);      // hi*hi
                    if (TERMS == 2)
                        mma16816(acc[mt][nt], Ahf[mt], Blf[q][h], Blf[q][h + 1]); // hi*lo
                }
            }
        }
        __syncthreads();
        issue(kt + NSTG); CP_COMMIT();
    }

    // ---- epilogue ----
#pragma unroll
    for (int mt = 0; mt < 4; mt++) {
        const int r0 = bm + wm + mt * 16 + (lane >> 2);
        if (OUTM == 3) {
            // exp epilogue: write unnormalized fp16 softmax numerators + rowsums
            float s0 = 0.f, s8 = 0.f;
#pragma unroll
            for (int nt = 0; nt < 8; nt++) {
                const int c0 = bn + wn + nt * 8 + (lane & 3) * 2;
                const float e00 = fminf(__expf(acc[mt][nt][0] - FSHIFT), 60000.f);
                const float e01 = fminf(__expf(acc[mt][nt][1] - FSHIFT), 60000.f);
                const float e10 = fminf(__expf(acc[mt][nt][2] - FSHIFT), 60000.f);
                const float e11 = fminf(__expf(acc[mt][nt][3] - FSHIFT), 60000.f);
                s0 += e00 + e01;  s8 += e10 + e11;
                *(uint32_t*)(Dh + (size_t)r0 * ldc + c0)       = cvt2h(e00, e01);
                *(uint32_t*)(Dh + (size_t)(r0 + 8) * ldc + c0) = cvt2h(e10, e11);
            }
            s0 += __shfl_xor_sync(0xffffffffu, s0, 1);
            s0 += __shfl_xor_sync(0xffffffffu, s0, 2);
            s8 += __shfl_xor_sync(0xffffffffu, s8, 1);
            s8 += __shfl_xor_sync(0xffffffffu, s8, 2);
            if ((lane & 3) == 0) {
                atomicAdd(&D[r0], s0);
                atomicAdd(&D[r0 + 8], s8);
            }
            continue;
        }
        if (OUTM == 4) {
            // fp32 out + channel statistics (rows are channels)
            float* csum = (float*)Dh;
            float* csq  = (float*)Dl;
            const float bv0 = (BMODE == 1) ? bias[r0]     : 0.f;
            const float bv8 = (BMODE == 1) ? bias[r0 + 8] : 0.f;
            float s0 = 0.f, q0 = 0.f, s8 = 0.f, q8 = 0.f;
#pragma unroll
            for (int nt = 0; nt < 8; nt++) {
                const int c0 = bn + wn + nt * 8 + (lane & 3) * 2;
                const float o00 = acc[mt][nt][0] + bv0;
                const float o01 = acc[mt][nt][1] + bv0;
                const float o10 = acc[mt][nt][2] + bv8;
                const float o11 = acc[mt][nt][3] + bv8;
                s0 += o00 + o01;  q0 += o00 * o00 + o01 * o01;
                s8 += o10 + o11;  q8 += o10 * o10 + o11 * o11;
                *(float2*)&D[(size_t)r0 * ldc + c0]       = make_float2(o00, o01);
                *(float2*)&D[(size_t)(r0 + 8) * ldc + c0] = make_float2(o10, o11);
            }
            s0 += __shfl_xor_sync(0xffffffffu, s0, 1);
            s0 += __shfl_xor_sync(0xffffffffu, s0, 2);
            q0 += __shfl_xor_sync(0xffffffffu, q0, 1);
            q0 += __shfl_xor_sync(0xffffffffu, q0, 2);
            s8 += __shfl_xor_sync(0xffffffffu, s8, 1);
            s8 += __shfl_xor_sync(0xffffffffu, s8, 2);
            q8 += __shfl_xor_sync(0xffffffffu, q8, 1);
            q8 += __shfl_xor_sync(0xffffffffu, q8, 2);
            if ((lane & 3) == 0) {
                atomicAdd(&csum[r0], s0);     atomicAdd(&csq[r0], q0);
                atomicAdd(&csum[r0 + 8], s8); atomicAdd(&csq[r0 + 8], q8);
            }
            continue;
        }
        const float bv0 = (BMODE == 1) ? bias[r0]     : 0.f;
        const float bv8 = (BMODE == 1) ? bias[r0 + 8] : 0.f;
        float sc0 = 1.f, sc8 = 1.f;
        if (BMODE == 3) { sc0 = 1.0f / bias[r0]; sc8 = 1.0f / bias[r0 + 8]; }
#pragma unroll
        for (int nt = 0; nt < 8; nt++) {
            const int c0 = bn + wn + nt * 8 + (lane & 3) * 2;
            float cb0 = 0.f, cb1 = 0.f;
            if (BMODE == 2) { const float2 bb = *(const float2*)&bias[c0]; cb0 = bb.x; cb1 = bb.y; }
            float o00 = acc[mt][nt][0] + bv0 + cb0;
            float o01 = acc[mt][nt][1] + bv0 + cb1;
            float o10 = acc[mt][nt][2] + bv8 + cb0;
            float o11 = acc[mt][nt][3] + bv8 + cb1;
            if (BMODE == 3) { o00 *= sc0; o01 *= sc0; o10 *= sc8; o11 *= sc8; }
            if (OUTM == 0) {
                *(float2*)&D[(size_t)r0 * ldc + c0]       = make_float2(o00, o01);
                *(float2*)&D[(size_t)(r0 + 8) * ldc + c0] = make_float2(o10, o11);
            } else if (OUTM == 1) {
                uint32_t h, l;
                split2(o00, o01, h, l);
                *(uint32_t*)(Dh + (size_t)r0 * ldc + c0) = h;
                *(uint32_t*)(Dl + (size_t)r0 * ldc + c0) = l;
                split2(o10, o11, h, l);
                *(uint32_t*)(Dh + (size_t)(r0 + 8) * ldc + c0) = h;
                *(uint32_t*)(Dl + (size_t)(r0 + 8) * ldc + c0) = l;
            } else {
                *(uint32_t*)(Dh + (size_t)r0 * ldc + c0)       = cvt2h(o00, o01);
                *(uint32_t*)(Dh + (size_t)(r0 + 8) * ldc + c0) = cvt2h(o10, o11);
            }
        }
    }
}

// ---------------- all weight splits in one launch ---------------------------
// blockIdx.y: 0=theta (hi+lo), 1=phi (hi+lo), 2=g (hi only), 3=wz (hi only)
__global__ __launch_bounds__(256)
void wsplit_all(const float* __restrict__ thw, const float* __restrict__ phw,
                const float* __restrict__ gw,  const float* __restrict__ wzw,
                __half* __restrict__ thh, __half* __restrict__ thl,
                __half* __restrict__ phh, __half* __restrict__ phl,
                __half* __restrict__ gh,  __half* __restrict__ wzh)
{
    const int p = blockIdx.x * 256 + threadIdx.x;
    const int w = blockIdx.y;
    const float* src = (w == 0) ? thw : (w == 1) ? phw : (w == 2) ? gw : wzw;
    const float2 v = *(const float2*)&src[2 * p];
    uint32_t h, l;
    split2(v.x, v.y, h, l);
    if (w == 0)      { ((uint32_t*)thh)[p] = h; ((uint32_t*)thl)[p] = l; }
    else if (w == 1) { ((uint32_t*)phh)[p] = h; ((uint32_t*)phl)[p] = l; }
    else if (w == 2) { ((uint32_t*)gh)[p]  = h; }
    else             { ((uint32_t*)wzh)[p] = h; }
}
// zero both fp32 accumulator buffers in one launch
__global__ __launch_bounds__(256)
void zero2_kernel(float* __restrict__ a, int na, float* __restrict__ b)
{
    const int i = blockIdx.x * 256 + threadIdx.x;
    if (i < na) a[i] = 0.f;
    else        b[i - na] = 0.f;
}

// ---------------- x (C,L) -> x^T hi/lo (L,C) transpose + split --------------
__global__ __launch_bounds__(256)
void xsplitT_kernel(const float* __restrict__ x,
                    __half* __restrict__ xh, __half* __restrict__ xl)
{
    __shared__ float t[32][33];
    const float* xb = x + (size_t)blockIdx.z * CCH * LTOK;
    const int lbase = blockIdx.x * 32;
    const int cbase = blockIdx.y * 32;
    const int tid = threadIdx.x;

    const int col = tid & 31, r0 = tid >> 5;
#pragma unroll
    for (int i = 0; i < 4; i++) {
        const int r = r0 + i * 8;
        t[r][col] = xb[(size_t)(cbase + r) * LTOK + lbase + col];
    }
    __syncthreads();

    const int cpair = (tid & 15) * 2;
    const int l0 = tid >> 4;
    const size_t obase = (size_t)blockIdx.z * LTOK * CCH;
#pragma unroll
    for (int i = 0; i < 2; i++) {
        const int l = l0 + i * 16;
        uint32_t h, lo;
        split2(t[cpair][l], t[cpair + 1][l], h, lo);
        const size_t o = (obase + (size_t)(lbase + l) * CCH + cbase + cpair) >> 1;
        ((uint32_t*)xh)[o] = h;
        ((uint32_t*)xl)[o] = lo;
    }
}

// ---------------- BN finalize (from fused channel stats) --------------------
__global__ __launch_bounds__(256)
void bn_finalize_kernel(const float* __restrict__ cstat,
                        float* __restrict__ mean, float* __restrict__ rstd)
{
    const int c = blockIdx.x * 256 + threadIdx.x;
    const float inv = 1.f / (float)(NBAT * LTOK);
    const float mu = cstat[c] * inv;
    const float var = cstat[CCH + c] * inv - mu * mu;
    mean[c] = mu;
    rstd[c] = rsqrtf(var + EPSV);
}

// ---------------- BN apply + residual ---------------------------------------
__global__ __launch_bounds__(256)
void bn_apply_kernel(const float* __restrict__ wy, const float* __restrict__ x,
                     const float* __restrict__ gamma, const float* __restrict__ beta,
                     const float* __restrict__ mean, const float* __restrict__ rstd,
                     float* __restrict__ out)
{
    const size_t i = (size_t)blockIdx.x * blockDim.x + threadIdx.x;
    const size_t base = i * 4;
    if (base >= (size_t)NBAT * CCH * LTOK) return;
    const int c = (int)((base >> 12) & (CCH - 1));
    const float4 w  = *(const float4*)(wy + base);
    const float4 xv = *(const float4*)(x + base);
    const float mu = mean[c];
    const float sc = rstd[c] * gamma[c];
    const float be = beta[c];
    float4 o;
    o.x = (w.x - mu) * sc + be + xv.x;
    o.y = (w.y - mu) * sc + be + xv.y;
    o.z = (w.z - mu) * sc + be + xv.z;
    o.w = (w.w - mu) * sc + be + xv.w;
    *(float4*)(out + base) = o;
}

// ---------------- launch ------------------------------------------------------
extern "C" void kernel_launch(void* const* d_in, const int* in_sizes, int n_in,
                              void* d_out, int out_size)
{
    const float* x     = (const float*)d_in[0];
    const float* g_w   = (const float*)d_in[1];
    const float* g_b   = (const float*)d_in[2];
    const float* th_w  = (const float*)d_in[3];
    const float* th_b  = (const float*)d_in[4];
    const float* ph_w  = (const float*)d_in[5];
    const float* ph_b  = (const float*)d_in[6];
    const float* wz_w  = (const float*)d_in[7];
    const float* wz_b  = (const float*)d_in[8];
    const float* gamma = (const float*)d_in[9];
    const float* beta  = (const float*)d_in[10];
    float* out = (float*)d_out;

    __half *p_xth, *p_xtl, *p_thwh, *p_thwl, *p_phwh, *p_phwl;
    __half *p_gwh, *p_wzh;
    __half *p_thh, *p_phh, *p_phl, *p_gh;
    __half *p_ph, *p_y2h;
    float *p_rsum, *p_wy, *p_cstat, *p_mean, *p_rstd;
    cudaGetSymbolAddress((void**)&p_xth,  d_xth);
    cudaGetSymbolAddress((void**)&p_xtl,  d_xtl);
    cudaGetSymbolAddress((void**)&p_thwh, d_thwh);
    cudaGetSymbolAddress((void**)&p_thwl, d_thwl);
    cudaGetSymbolAddress((void**)&p_phwh, d_phwh);
    cudaGetSymbolAddress((void**)&p_phwl, d_phwl);
    cudaGetSymbolAddress((void**)&p_gwh,  d_gwh);
    cudaGetSymbolAddress((void**)&p_wzh,  d_wzh);
    cudaGetSymbolAddress((void**)&p_thh,  d_thh);
    cudaGetSymbolAddress((void**)&p_phh,  d_phh);
    cudaGetSymbolAddress((void**)&p_phl,  d_phl);
    cudaGetSymbolAddress((void**)&p_gh,   d_gh);
    cudaGetSymbolAddress((void**)&p_ph,   d_ph_);
    cudaGetSymbolAddress((void**)&p_rsum, d_rsum);
    cudaGetSymbolAddress((void**)&p_y2h,  d_y2h);
    cudaGetSymbolAddress((void**)&p_wy,   d_wy);
    cudaGetSymbolAddress((void**)&p_cstat, d_cstat);
    cudaGetSymbolAddress((void**)&p_mean, d_mean);
    cudaGetSymbolAddress((void**)&p_rstd, d_rstd);

    constexpr int GS_P2  = 2 * 3 * 128 * 36 * 4;          // 110592 (proj, 128x128)
    constexpr int GS_F   = 2 * (256 + 256) * 36 * 4;      // 147456 (f, 256x128 T2)
    constexpr int GS_Y2  = 3 * (128 + 256) * 36 * 4;      // 165888 (y2, 128x256 T1)
    constexpr int GS_WZ  = 3 * 2 * 128 * 36 * 4;          // 110592 (wz, 128x128 T1)
    cudaFuncSetAttribute(gemm_pre<2, 2, 2, 128, 128>, cudaFuncAttributeMaxDynamicSharedMemorySize, GS_P2);
    cudaFuncSetAttribute(gemm_pre<2, 1, 2, 128, 128>, cudaFuncAttributeMaxDynamicSharedMemorySize, GS_P2);
    cudaFuncSetAttribute(gemm_pre<2, 2, 1, 128, 128>, cudaFuncAttributeMaxDynamicSharedMemorySize, GS_P2);
    cudaFuncSetAttribute(gemm_pre<2, 3, 0, 256, 128>, cudaFuncAttributeMaxDynamicSharedMemorySize, GS_F);
    cudaFuncSetAttribute(gemm_pre<1, 2, 3, 128, 256>, cudaFuncAttributeMaxDynamicSharedMemorySize, GS_Y2);
    cudaFuncSetAttribute(gemm_pre<1, 4, 1, 128, 128>, cudaFuncAttributeMaxDynamicSharedMemorySize, GS_WZ);

    const dim3 b128(128), b256(256);
    const long long sXT = (long long)LTOK * CCH;  // xT stride
    const long long sT  = (long long)LTOK * CIN;  // thetaT/phiT/y2 stride
    const long long sG  = (long long)CIN * LTOK;  // g stride
    const long long sF  = (long long)LTOK * LTOK; // P stride
    const long long sW  = (long long)CCH * LTOK;  // wy stride

    // 0) split weights (one launch) + transpose-split x + zero accumulators
    {
        dim3 g(CIN * CCH / 512, 4);
        wsplit_all<<<g, b256>>>(th_w, ph_w, g_w, wz_w,
                                p_thwh, p_thwl, p_phwh, p_phwl,
                                p_gwh, p_wzh);
    }
    zero2_kernel<<<(NBAT * LTOK + 2 * CCH) / 256, b256>>>(p_rsum, NBAT * LTOK, p_cstat);
    {
        dim3 g(LTOK / 32, CCH / 32, NBAT);
        xsplitT_kernel<<<g, b256>>>(x, p_xth, p_xtl);
    }

    // 1) projections — 2-term, 128x128
    {
        dim3 g(CIN / 128, LTOK / 128, NBAT);
        gemm_pre<2, 2, 2, 128, 128><<<g, b128, GS_P2>>>(p_xth, CCH, sXT,
                                                        p_thwh, p_thwl, CCH, 0,
                                                        nullptr, p_thh, nullptr, CIN, sT,
                                                        th_b, CCH);
        gemm_pre<2, 1, 2, 128, 128><<<g, b128, GS_P2>>>(p_xth, CCH, sXT,
                                                        p_phwh, p_phwl, CCH, 0,
                                                        nullptr, p_phh, p_phl, CIN, sT,
                                                        ph_b, CCH);
    }
    {
        dim3 g(LTOK / 128, CIN / 128, NBAT);
        gemm_pre<2, 2, 1, 128, 128><<<g, b128, GS_P2>>>(p_gwh, CCH, 0,
                                                        p_xth, p_xtl, CCH, sXT,
                                                        nullptr, p_gh, nullptr, LTOK, sG,
                                                        g_b, CCH);
    }
    // 2) P = exp(theta_hi · phi^T − 12) fp16 + fp32 rowsums — 256x128 tile
    {
        dim3 g(LTOK / 128, LTOK / 256, NBAT);
        gemm_pre<2, 3, 0, 256, 128><<<g, b256, GS_F>>>(p_thh, CIN, sT,
                                                       p_phh, p_phl, CIN, sT,
                                                       p_rsum, p_ph, nullptr, LTOK, sF,
                                                       nullptr, CIN);
    }
    // 3) y2 (L x CI) = (P_hi · g_hi^T) / rowsum — 128x256 tile (P read once)
    {
        dim3 g(CIN / 256, LTOK / 128, NBAT);
        gemm_pre<1, 2, 3, 128, 256><<<g, b256, GS_Y2>>>(p_ph, LTOK, sF,
                                                        p_gh, nullptr, LTOK, sG,
                                                        nullptr, p_y2h, nullptr, CIN, sT,
                                                        p_rsum, LTOK);
    }
    // 4) w_y = Wz_hi · y2_hi^T + bias — 1-term 3-stage, fused channel stats
    {
        dim3 g(LTOK / 128, CCH / 128, NBAT);
        gemm_pre<1, 4, 1, 128, 128><<<g, b128, GS_WZ>>>(p_wzh, CIN, 0,
                                                        p_y2h, nullptr, CIN, sT,
                                                        p_wy, (__half*)p_cstat,
                                                        (__half*)(p_cstat + CCH), LTOK, sW,
                                                        wz_b, CIN);
    }
    // 5) BN finalize
    bn_finalize_kernel<<<CCH / 256, b256>>>(p_cstat, p_mean, p_rstd);
    // 6) BN apply + residual
    {
        const size_t total4 = (size_t)NBAT * CCH * LTOK / 4;
        bn_apply_kernel<<<(unsigned)((total4 + 255) / 256), b256>>>(
            p_wy, x, gamma, beta, p_mean, p_rstd, out);
    }
}

// round 17
// speedup vs baseline: 1.0984x; 1.0984x over previous
#include <cuda_runtime.h>
#include <cuda_fp16.h>
#include <cstdint>
#include <cstddef>

#define LTOK 4096   // H*W tokens
#define CCH  512    // in channels
#define CIN  256    // inter channels
#define NBAT 4      // batch
#define EPSV 1e-5f
#define FSHIFT 12.0f

// ---------------- scratch (device globals: no runtime allocation) ----------
__device__ __half d_xth[(size_t)NBAT * LTOK * CCH];  // x^T hi (L,C)
__device__ __half d_xtl[(size_t)NBAT * LTOK * CCH];  // x^T lo
__device__ __half d_thwh[CIN * CCH], d_thwl[CIN * CCH];
__device__ __half d_phwh[CIN * CCH], d_phwl[CIN * CCH];
__device__ __half d_gwh [CIN * CCH];
__device__ __half d_wzh [CCH * CIN];
__device__ __half d_thh[(size_t)NBAT * LTOK * CIN];  // theta^T hi only (L,CI)
__device__ __half d_phh[(size_t)NBAT * LTOK * CIN];  // phi^T hi
__device__ __half d_phl[(size_t)NBAT * LTOK * CIN];  // phi^T lo
__device__ __half d_gh [(size_t)NBAT * CIN * LTOK];  // g hi only (CI,L)
__device__ __half d_ph_[(size_t)NBAT * LTOK * LTOK]; // unnormalized exp(f-12) fp16
__device__ float  d_rsum[(size_t)NBAT * LTOK];       // softmax row sums
__device__ __half d_y2h[(size_t)NBAT * LTOK * CIN];  // y2 hi only (L,CI)
__device__ float d_wy[(size_t)NBAT * CCH * LTOK];
__device__ float d_cstat[2 * CCH];                   // channel sum / sumsq
__device__ float d_mean[CCH];
__device__ float d_rstd[CCH];

// =========================== helpers ========================================
__device__ __forceinline__ uint32_t smem_u32(const void* p) {
    uint32_t a;
    asm("{ .reg .u64 t; cvta.to.shared.u64 t, %1; cvt.u32.u64 %0, t; }" : "=r"(a) : "l"(p));
    return a;
}
// pack two fp32 into f16x2 (x -> low 16 bits, y -> high 16 bits)
__device__ __forceinline__ uint32_t cvt2h(float x, float y) {
    uint32_t r;
    asm("cvt.rn.f16x2.f32 %0, %1, %2;" : "=r"(r) : "f"(y), "f"(x));
    return r;
}
__device__ __forceinline__ void split2(float x, float y, uint32_t& h, uint32_t& l) {
    h = cvt2h(x, y);
    const float hx = __half2float(__ushort_as_half((unsigned short)(h & 0xffffu)));
    const float hy = __half2float(__ushort_as_half((unsigned short)(h >> 16)));
    l = cvt2h(x - hx, y - hy);
}
__device__ __forceinline__ void mma16816(float c[4], const uint32_t a[4],
                                         uint32_t b0, uint32_t b1) {
    asm volatile(
        "mma.sync.aligned.m16n8k16.row.col.f32.f16.f16.f32 "
        "{%0,%1,%2,%3}, {%4,%5,%6,%7}, {%8,%9}, {%0,%1,%2,%3};"
        : "+f"(c[0]), "+f"(c[1]), "+f"(c[2]), "+f"(c[3])
        : "r"(a[0]), "r"(a[1]), "r"(a[2]), "r"(a[3]), "r"(b0), "r"(b1));
}
__device__ __forceinline__ void ldm4(uint32_t r[4], uint32_t addr) {
    asm volatile("ldmatrix.sync.aligned.m8n8.x4.shared.b16 {%0,%1,%2,%3}, [%4];"
        : "=r"(r[0]), "=r"(r[1]), "=r"(r[2]), "=r"(r[3]) : "r"(addr));
}
__device__ __forceinline__ void cp16(uint32_t dst, const void* src) {
    asm volatile("cp.async.cg.shared.global [%0], [%1], 16;" :: "r"(dst), "l"(src) : "memory");
}
#define CP_COMMIT() asm volatile("cp.async.commit_group;" ::: "memory")
template<int N>
__device__ __forceinline__ void cp_wait() {
    asm volatile("cp.async.wait_group %0;" :: "n"(N) : "memory");
}

// ============ unified GEMM: fp16 split inputs, cp.async pipeline ============
// TERMS==2: D = Ah·(Bh+Bl)^T (A quantized fp16),  K-step 64, 2 stages
// TERMS==1: D = Ah·Bh^T (both quantized fp16),    K-step 64, 3 stages
// Row-major K-contig. CTA tile 128x128, 128 threads (64x64 per warp),
// 2 CTAs/SM. Fragments via ldmatrix.x4 (non-trans).
// OUTM 0: fp32 D; 1: half Dh+Dl; 2: half Dh only;
// OUTM 3: exp epilogue — Dh = fp16 exp(acc-FSHIFT), D = fp32 rowsum atomics.
// OUTM 4: fp32 D + per-row (channel) sum/sumsq atomics into
//         csum=(float*)Dh, csq=(float*)Dl (shared across batch).
// BMODE 0: none, 1: bias per-M-row, 2: bias per-N-col,
// BMODE 3: row-scale by 1/bias[row] (bias = rowsum, batch stride LTOK).

template<int TERMS, int OUTM, int BMODE>
__global__ void __launch_bounds__(128, 2)
gemm_pre(const __half* __restrict__ Ah,
         int lda, long long sA,
         const __half* __restrict__ Bh, const __half* __restrict__ Bl,
         int ldb, long long sB,
         float* __restrict__ D, __half* __restrict__ Dh,
         __half* __restrict__ Dl, int ldc, long long sD,
         const float* __restrict__ bias, int K)
{
    constexpr int KS   = 64;                      // K per stage
    constexpr int CW   = KS / 2;                  // u32 per row (data)
    constexpr int STR  = CW + 4;                  // padded row stride (u32)
    constexpr int CPR  = CW / 4;                  // 16B chunks per row
    constexpr int SMU  = 128 * STR;               // u32 per matrix
    constexpr int gAH  = 0;
    constexpr int gBH  = SMU;
    constexpr int gBL  = 2 * SMU;                 // TERMS==2 only
    constexpr int STG  = (TERMS == 2 ? 3 : 2) * SMU;
    constexpr int NSTG = (TERMS == 1) ? 3 : 2;
    constexpr int SSN  = KS / 16;

    extern __shared__ uint32_t sm[];
    const uint32_t sbase = smem_u32(sm);
    Ah += (size_t)blockIdx.z * sA;
    Bh += (size_t)blockIdx.z * sB;
    if (TERMS == 2) Bl += (size_t)blockIdx.z * sB;
    if (OUTM == 0 || OUTM == 4) D += (size_t)blockIdx.z * sD;
    else if (OUTM == 3) { Dh += (size_t)blockIdx.z * sD; D += (size_t)blockIdx.z * LTOK; }
    else { Dh += (size_t)blockIdx.z * sD; if (OUTM == 1) Dl += (size_t)blockIdx.z * sD; }
    if (BMODE == 3) bias += (size_t)blockIdx.z * LTOK;

    const int bm = blockIdx.y * 128;
    const int bn = blockIdx.x * 128;
    const int tid  = threadIdx.x;
    const int lane = tid & 31;
    const int wid  = tid >> 5;
    const int wm = (wid & 1) * 64;    // 2 warps in M
    const int wn = (wid >> 1) * 64;   // 2 warps in N

    float acc[4][8][4];
#pragma unroll
    for (int a = 0; a < 4; a++)
#pragma unroll
        for (int b = 0; b < 8; b++)
#pragma unroll
            for (int c = 0; c < 4; c++) acc[a][b][c] = 0.f;

    const int KT = K / KS;

    auto issue = [&](int kt) {
        if (kt >= KT) return;
        const uint32_t sb = sbase + (uint32_t)(kt % NSTG) * (STG * 4);
        const int k0 = kt * KS;
#pragma unroll
        for (int p = 0; p < CPR; p++) {
            const int c = tid + p * 128;
            const int r = c / CPR;
            const int cc = c % CPR;
            const uint32_t d = sb + (uint32_t)((r * STR + cc * 4) << 2);
            const size_t goA = (size_t)(bm + r) * lda + k0 + cc * 8;
            const size_t goB = (size_t)(bn + r) * ldb + k0 + cc * 8;
            cp16(d + gAH * 4, Ah + goA);
            cp16(d + gBH * 4, Bh + goB);
            if (TERMS == 2) cp16(d + gBL * 4, Bl + goB);
        }
    };

#pragma unroll
    for (int s = 0; s < NSTG; s++) { issue(s); CP_COMMIT(); }

    // ldmatrix lane geometry (non-trans x4)
    const int aRow = (lane & 7) + (lane & 8);          // A: tiles (row-half, k-half)
    const int aCol = (lane >> 4) * 4;
    const int bRow = (lane & 7) + ((lane & 16) >> 1);  // B: tiles (k-half, n-half)
    const int bCol = ((lane >> 3) & 1) * 4;

    for (int kt = 0; kt < KT; kt++) {
        cp_wait<NSTG - 1>();
        __syncthreads();
        const uint32_t sb = sbase + (uint32_t)(kt % NSTG) * (STG * 4);
        uint32_t aBh[4], bB_h[4], bB_l[4];
#pragma unroll
        for (int mt = 0; mt < 4; mt++) {
            const uint32_t ro = (uint32_t)((wm + mt * 16 + aRow) * STR + aCol) * 4;
            aBh[mt] = sb + gAH * 4 + ro;
        }
#pragma unroll
        for (int np = 0; np < 4; np++) {
            const uint32_t ro = (uint32_t)((wn + np * 16 + bRow) * STR + bCol) * 4;
            bB_h[np] = sb + gBH * 4 + ro;
            if (TERMS == 2) bB_l[np] = sb + gBL * 4 + ro;
        }
#pragma unroll
        for (int ss = 0; ss < SSN; ss++) {
            const uint32_t o = ss * 32;   // 8 u32 per k16 step
            uint32_t Ahf[4][4], Bhf[4][4], Blf[4][4];
#pragma unroll
            for (int mt = 0; mt < 4; mt++) ldm4(Ahf[mt], aBh[mt] + o);
#pragma unroll
            for (int np = 0; np < 4; np++) {
                ldm4(Bhf[np], bB_h[np] + o);
                if (TERMS == 2) ldm4(Blf[np], bB_l[np] + o);
            }
#pragma unroll
            for (int nt = 0; nt < 8; nt++) {
                const int q = nt >> 1, h = (nt & 1) * 2;
                const uint32_t b0h = Bhf[q][h], b1h = Bhf[q][h + 1];
#pragma unroll
                for (int mt = 0; mt < 4; mt++) {
                    mma16816(acc[mt][nt], Ahf[mt], b0h, b1h);      // hi*hi
                    if (TERMS == 2)
                        mma16816(acc[mt][nt], Ahf[mt], Blf[q][h], Blf[q][h + 1]); // hi*lo
                }
            }
        }
        __syncthreads();
        issue(kt + NSTG); CP_COMMIT();
    }

    // ---- epilogue ----
#pragma unroll
    for (int mt = 0; mt < 4; mt++) {
        const int r0 = bm + wm + mt * 16 + (lane >> 2);
        if (OUTM == 3) {
            // exp epilogue: write unnormalized fp16 softmax numerators + rowsums
            float s0 = 0.f, s8 = 0.f;
#pragma unroll
            for (int nt = 0; nt < 8; nt++) {
                const int c0 = bn + wn + nt * 8 + (lane & 3) * 2;
                const float e00 = fminf(__expf(acc[mt][nt][0] - FSHIFT), 60000.f);
                const float e01 = fminf(__expf(acc[mt][nt][1] - FSHIFT), 60000.f);
                const float e10 = fminf(__expf(acc[mt][nt][2] - FSHIFT), 60000.f);
                const float e11 = fminf(__expf(acc[mt][nt][3] - FSHIFT), 60000.f);
                s0 += e00 + e01;  s8 += e10 + e11;
                *(uint32_t*)(Dh + (size_t)r0 * ldc + c0)       = cvt2h(e00, e01);
                *(uint32_t*)(Dh + (size_t)(r0 + 8) * ldc + c0) = cvt2h(e10, e11);
            }
            s0 += __shfl_xor_sync(0xffffffffu, s0, 1);
            s0 += __shfl_xor_sync(0xffffffffu, s0, 2);
            s8 += __shfl_xor_sync(0xffffffffu, s8, 1);
            s8 += __shfl_xor_sync(0xffffffffu, s8, 2);
            if ((lane & 3) == 0) {
                atomicAdd(&D[r0], s0);
                atomicAdd(&D[r0 + 8], s8);
            }
            continue;
        }
        if (OUTM == 4) {
            // fp32 out + channel statistics (rows are channels)
            float* csum = (float*)Dh;
            float* csq  = (float*)Dl;
            const float bv0 = (BMODE == 1) ? bias[r0]     : 0.f;
            const float bv8 = (BMODE == 1) ? bias[r0 + 8] : 0.f;
            float s0 = 0.f, q0 = 0.f, s8 = 0.f, q8 = 0.f;
#pragma unroll
            for (int nt = 0; nt < 8; nt++) {
                const int c0 = bn + wn + nt * 8 + (lane & 3) * 2;
                const float o00 = acc[mt][nt][0] + bv0;
                const float o01 = acc[mt][nt][1] + bv0;
                const float o10 = acc[mt][nt][2] + bv8;
                const float o11 = acc[mt][nt][3] + bv8;
                s0 += o00 + o01;  q0 += o00 * o00 + o01 * o01;
                s8 += o10 + o11;  q8 += o10 * o10 + o11 * o11;
                *(float2*)&D[(size_t)r0 * ldc + c0]       = make_float2(o00, o01);
                *(float2*)&D[(size_t)(r0 + 8) * ldc + c0] = make_float2(o10, o11);
            }
            s0 += __shfl_xor_sync(0xffffffffu, s0, 1);
            s0 += __shfl_xor_sync(0xffffffffu, s0, 2);
            q0 += __shfl_xor_sync(0xffffffffu, q0, 1);
            q0 += __shfl_xor_sync(0xffffffffu, q0, 2);
            s8 += __shfl_xor_sync(0xffffffffu, s8, 1);
            s8 += __shfl_xor_sync(0xffffffffu, s8, 2);
            q8 += __shfl_xor_sync(0xffffffffu, q8, 1);
            q8 += __shfl_xor_sync(0xffffffffu, q8, 2);
            if ((lane & 3) == 0) {
                atomicAdd(&csum[r0], s0);     atomicAdd(&csq[r0], q0);
                atomicAdd(&csum[r0 + 8], s8); atomicAdd(&csq[r0 + 8], q8);
            }
            continue;
        }
        const float bv0 = (BMODE == 1) ? bias[r0]     : 0.f;
        const float bv8 = (BMODE == 1) ? bias[r0 + 8] : 0.f;
        float sc0 = 1.f, sc8 = 1.f;
        if (BMODE == 3) { sc0 = 1.0f / bias[r0]; sc8 = 1.0f / bias[r0 + 8]; }
#pragma unroll
        for (int nt = 0; nt < 8; nt++) {
            const int c0 = bn + wn + nt * 8 + (lane & 3) * 2;
            float cb0 = 0.f, cb1 = 0.f;
            if (BMODE == 2) { const float2 bb = *(const float2*)&bias[c0]; cb0 = bb.x; cb1 = bb.y; }
            float o00 = acc[mt][nt][0] + bv0 + cb0;
            float o01 = acc[mt][nt][1] + bv0 + cb1;
            float o10 = acc[mt][nt][2] + bv8 + cb0;
            float o11 = acc[mt][nt][3] + bv8 + cb1;
            if (BMODE == 3) { o00 *= sc0; o01 *= sc0; o10 *= sc8; o11 *= sc8; }
            if (OUTM == 0) {
                *(float2*)&D[(size_t)r0 * ldc + c0]       = make_float2(o00, o01);
                *(float2*)&D[(size_t)(r0 + 8) * ldc + c0] = make_float2(o10, o11);
            } else if (OUTM == 1) {
                uint32_t h, l;
                split2(o00, o01, h, l);
                *(uint32_t*)(Dh + (size_t)r0 * ldc + c0) = h;
                *(uint32_t*)(Dl + (size_t)r0 * ldc + c0) = l;
                split2(o10, o11, h, l);
                *(uint32_t*)(Dh + (size_t)(r0 + 8) * ldc + c0) = h;
                *(uint32_t*)(Dl + (size_t)(r0 + 8) * ldc + c0) = l;
            } else {
                *(uint32_t*)(Dh + (size_t)r0 * ldc + c0)       = cvt2h(o00, o01);
                *(uint32_t*)(Dh + (size_t)(r0 + 8) * ldc + c0) = cvt2h(o10, o11);
            }
        }
    }
}

// ---------------- all weight splits in one launch ---------------------------
// blockIdx.y: 0=theta (hi+lo), 1=phi (hi+lo), 2=g (hi only), 3=wz (hi only)
__global__ __launch_bounds__(256)
void wsplit_all(const float* __restrict__ thw, const float* __restrict__ phw,
                const float* __restrict__ gw,  const float* __restrict__ wzw,
                __half* __restrict__ thh, __half* __restrict__ thl,
                __half* __restrict__ phh, __half* __restrict__ phl,
                __half* __restrict__ gh,  __half* __restrict__ wzh)
{
    const int p = blockIdx.x * 256 + threadIdx.x;
    const int w = blockIdx.y;
    const float* src = (w == 0) ? thw : (w == 1) ? phw : (w == 2) ? gw : wzw;
    const float2 v = *(const float2*)&src[2 * p];
    uint32_t h, l;
    split2(v.x, v.y, h, l);
    if (w == 0)      { ((uint32_t*)thh)[p] = h; ((uint32_t*)thl)[p] = l; }
    else if (w == 1) { ((uint32_t*)phh)[p] = h; ((uint32_t*)phl)[p] = l; }
    else if (w == 2) { ((uint32_t*)gh)[p]  = h; }
    else             { ((uint32_t*)wzh)[p] = h; }
}
// zero both fp32 accumulator buffers in one launch
__global__ __launch_bounds__(256)
void zero2_kernel(float* __restrict__ a, int na, float* __restrict__ b)
{
    const int i = blockIdx.x * 256 + threadIdx.x;
    if (i < na) a[i] = 0.f;
    else        b[i - na] = 0.f;
}

// ---------------- x (C,L) -> x^T hi/lo (L,C) transpose + split --------------
__global__ __launch_bounds__(256)
void xsplitT_kernel(const float* __restrict__ x,
                    __half* __restrict__ xh, __half* __restrict__ xl)
{
    __shared__ float t[32][33];
    const float* xb = x + (size_t)blockIdx.z * CCH * LTOK;
    const int lbase = blockIdx.x * 32;
    const int cbase = blockIdx.y * 32;
    const int tid = threadIdx.x;

    const int col = tid & 31, r0 = tid >> 5;
#pragma unroll
    for (int i = 0; i < 4; i++) {
        const int r = r0 + i * 8;
        t[r][col] = xb[(size_t)(cbase + r) * LTOK + lbase + col];
    }
    __syncthreads();

    const int cpair = (tid & 15) * 2;
    const int l0 = tid >> 4;
    const size_t obase = (size_t)blockIdx.z * LTOK * CCH;
#pragma unroll
    for (int i = 0; i < 2; i++) {
        const int l = l0 + i * 16;
        uint32_t h, lo;
        split2(t[cpair][l], t[cpair + 1][l], h, lo);
        const size_t o = (obase + (size_t)(lbase + l) * CCH + cbase + cpair) >> 1;
        ((uint32_t*)xh)[o] = h;
        ((uint32_t*)xl)[o] = lo;
    }
}

// ---------------- BN finalize (from fused channel stats) --------------------
__global__ __launch_bounds__(256)
void bn_finalize_kernel(const float* __restrict__ cstat,
                        float* __restrict__ mean, float* __restrict__ rstd)
{
    const int c = blockIdx.x * 256 + threadIdx.x;
    const float inv = 1.f / (float)(NBAT * LTOK);
    const float mu = cstat[c] * inv;
    const float var = cstat[CCH + c] * inv - mu * mu;
    mean[c] = mu;
    rstd[c] = rsqrtf(var + EPSV);
}

// ---------------- BN apply + residual ---------------------------------------
__global__ __launch_bounds__(256)
void bn_apply_kernel(const float* __restrict__ wy, const float* __restrict__ x,
                     const float* __restrict__ gamma, const float* __restrict__ beta,
                     const float* __restrict__ mean, const float* __restrict__ rstd,
                     float* __restrict__ out)
{
    const size_t i = (size_t)blockIdx.x * blockDim.x + threadIdx.x;
    const size_t base = i * 4;
    if (base >= (size_t)NBAT * CCH * LTOK) return;
    const int c = (int)((base >> 12) & (CCH - 1));
    const float4 w  = *(const float4*)(wy + base);
    const float4 xv = *(const float4*)(x + base);
    const float mu = mean[c];
    const float sc = rstd[c] * gamma[c];
    const float be = beta[c];
    float4 o;
    o.x = (w.x - mu) * sc + be + xv.x;
    o.y = (w.y - mu) * sc + be + xv.y;
    o.z = (w.z - mu) * sc + be + xv.z;
    o.w = (w.w - mu) * sc + be + xv.w;
    *(float4*)(out + base) = o;
}

// ---------------- launch ------------------------------------------------------
extern "C" void kernel_launch(void* const* d_in, const int* in_sizes, int n_in,
                              void* d_out, int out_size)
{
    const float* x     = (const float*)d_in[0];
    const float* g_w   = (const float*)d_in[1];
    const float* g_b   = (const float*)d_in[2];
    const float* th_w  = (const float*)d_in[3];
    const float* th_b  = (const float*)d_in[4];
    const float* ph_w  = (const float*)d_in[5];
    const float* ph_b  = (const float*)d_in[6];
    const float* wz_w  = (const float*)d_in[7];
    const float* wz_b  = (const float*)d_in[8];
    const float* gamma = (const float*)d_in[9];
    const float* beta  = (const float*)d_in[10];
    float* out = (float*)d_out;

    __half *p_xth, *p_xtl, *p_thwh, *p_thwl, *p_phwh, *p_phwl;
    __half *p_gwh, *p_wzh;
    __half *p_thh, *p_phh, *p_phl, *p_gh;
    __half *p_ph, *p_y2h;
    float *p_rsum, *p_wy, *p_cstat, *p_mean, *p_rstd;
    cudaGetSymbolAddress((void**)&p_xth,  d_xth);
    cudaGetSymbolAddress((void**)&p_xtl,  d_xtl);
    cudaGetSymbolAddress((void**)&p_thwh, d_thwh);
    cudaGetSymbolAddress((void**)&p_thwl, d_thwl);
    cudaGetSymbolAddress((void**)&p_phwh, d_phwh);
    cudaGetSymbolAddress((void**)&p_phwl, d_phwl);
    cudaGetSymbolAddress((void**)&p_gwh,  d_gwh);
    cudaGetSymbolAddress((void**)&p_wzh,  d_wzh);
    cudaGetSymbolAddress((void**)&p_thh,  d_thh);
    cudaGetSymbolAddress((void**)&p_phh,  d_phh);
    cudaGetSymbolAddress((void**)&p_phl,  d_phl);
    cudaGetSymbolAddress((void**)&p_gh,   d_gh);
    cudaGetSymbolAddress((void**)&p_ph,   d_ph_);
    cudaGetSymbolAddress((void**)&p_rsum, d_rsum);
    cudaGetSymbolAddress((void**)&p_y2h,  d_y2h);
    cudaGetSymbolAddress((void**)&p_wy,   d_wy);
    cudaGetSymbolAddress((void**)&p_cstat, d_cstat);
    cudaGetSymbolAddress((void**)&p_mean, d_mean);
    cudaGetSymbolAddress((void**)&p_rstd, d_rstd);

    constexpr int GSMEM2 = 2 * 3 * 128 * 36 * 4;   // 110592 (2 stages x 3 mats)
    constexpr int GSMEM1 = 3 * 2 * 128 * 36 * 4;   // 110592 (3 stages x 2 mats)
    cudaFuncSetAttribute(gemm_pre<2, 2, 2>, cudaFuncAttributeMaxDynamicSharedMemorySize, GSMEM2);
    cudaFuncSetAttribute(gemm_pre<2, 1, 2>, cudaFuncAttributeMaxDynamicSharedMemorySize, GSMEM2);
    cudaFuncSetAttribute(gemm_pre<2, 2, 1>, cudaFuncAttributeMaxDynamicSharedMemorySize, GSMEM2);
    cudaFuncSetAttribute(gemm_pre<2, 3, 0>, cudaFuncAttributeMaxDynamicSharedMemorySize, GSMEM2);
    cudaFuncSetAttribute(gemm_pre<1, 2, 3>, cudaFuncAttributeMaxDynamicSharedMemorySize, GSMEM1);
    cudaFuncSetAttribute(gemm_pre<1, 4, 1>, cudaFuncAttributeMaxDynamicSharedMemorySize, GSMEM1);

    const dim3 b128(128), b256(256);
    const long long sXT = (long long)LTOK * CCH;  // xT stride
    const long long sT  = (long long)LTOK * CIN;  // thetaT/phiT/y2 stride
    const long long sG  = (long long)CIN * LTOK;  // g stride
    const long long sF  = (long long)LTOK * LTOK; // P stride
    const long long sW  = (long long)CCH * LTOK;  // wy stride

    // 0) split weights (one launch) + transpose-split x + zero accumulators
    {
        dim3 g(CIN * CCH / 512, 4);
        wsplit_all<<<g, b256>>>(th_w, ph_w, g_w, wz_w,
                                p_thwh, p_thwl, p_phwh, p_phwl,
                                p_gwh, p_wzh);
    }
    zero2_kernel<<<(NBAT * LTOK + 2 * CCH) / 256, b256>>>(p_rsum, NBAT * LTOK, p_cstat);
    {
        dim3 g(LTOK / 32, CCH / 32, NBAT);
        xsplitT_kernel<<<g, b256>>>(x, p_xth, p_xtl);
    }

    // 1) projections — 2-term
    //    thetaT (L x CI) = xT_hi · (Wth_h + Wth_l)^T, hi-only out, col bias
    {
        dim3 g(CIN / 128, LTOK / 128, NBAT);
        gemm_pre<2, 2, 2><<<g, b128, GSMEM2>>>(p_xth, CCH, sXT,
                                               p_thwh, p_thwl, CCH, 0,
                                               nullptr, p_thh, nullptr, CIN, sT,
                                               th_b, CCH);
        //    phiT (L x CI): wide out (hi+lo), col bias
        gemm_pre<2, 1, 2><<<g, b128, GSMEM2>>>(p_xth, CCH, sXT,
                                               p_phwh, p_phwl, CCH, 0,
                                               nullptr, p_phh, p_phl, CIN, sT,
                                               ph_b, CCH);
    }
    //    g (CI x L) = Wg_hi · (xT_h + xT_l)^T, hi-only out, row bias
    {
        dim3 g(LTOK / 128, CIN / 128, NBAT);
        gemm_pre<2, 2, 1><<<g, b128, GSMEM2>>>(p_gwh, CCH, 0,
                                               p_xth, p_xtl, CCH, sXT,
                                               nullptr, p_gh, nullptr, LTOK, sG,
                                               g_b, CCH);
    }
    // 2) P = exp(theta_hi · phi^T − 12) fp16 + fp32 rowsums (fused softmax pt 1)
    {
        dim3 g(LTOK / 128, LTOK / 128, NBAT);
        gemm_pre<2, 3, 0><<<g, b128, GSMEM2>>>(p_thh, CIN, sT,
                                               p_phh, p_phl, CIN, sT,
                                               p_rsum, p_ph, nullptr, LTOK, sF,
                                               nullptr, CIN);
    }
    // 3) y2 (L x CI) = (P_hi · g_hi^T) / rowsum — 1-term 3-stage, hi-only out
    {
        dim3 g(CIN / 128, LTOK / 128, NBAT);
        gemm_pre<1, 2, 3><<<g, b128, GSMEM1>>>(p_ph, LTOK, sF,
                                               p_gh, nullptr, LTOK, sG,
                                               nullptr, p_y2h, nullptr, CIN, sT,
                                               p_rsum, LTOK);
    }
    // 4) w_y = Wz_hi · y2_hi^T + bias — 1-term 3-stage, fused channel stats
    {
        dim3 g(LTOK / 128, CCH / 128, NBAT);
        gemm_pre<1, 4, 1><<<g, b128, GSMEM1>>>(p_wzh, CIN, 0,
                                               p_y2h, nullptr, CIN, sT,
                                               p_wy, (__half*)p_cstat,
                                               (__half*)(p_cstat + CCH), LTOK, sW,
                                               wz_b, CIN);
    }
    // 5) BN finalize
    bn_finalize_kernel<<<CCH / 256, b256>>>(p_cstat, p_mean, p_rstd);
    // 6) BN apply + residual
    {
        const size_t total4 = (size_t)NBAT * CCH * LTOK / 4;
        bn_apply_kernel<<<(unsigned)((total4 + 255) / 256), b256>>>(
            p_wy, x, gamma, beta, p_mean, p_rstd, out);
    }
}